// round 1
// baseline (speedup 1.0000x reference)
#include <cuda_runtime.h>
#include <math.h>

// Shapes (fixed by the problem)
#define BB 2
#define SS 128
#define DD 64
#define FF 256
#define DD2 (DD*DD)
#define NJG 64          // j-groups (2 j's per CTA) for split-K
#define KC 32           // f-chunk in main kernel

typedef unsigned long long u64;

// -------- scratch (device globals: sanctioned, no runtime alloc) --------
__device__ float g_A[BB*SS*FF];              // A[b,i,f]
__device__ float g_C[BB*SS*FF];              // C[b,j,f] (includes gb1)
__device__ float g_W[BB*SS*FF*DD];           // W[b,j,f,e]  16 MB
__device__ float g_Pagg[BB*NJG*SS*DD];       // partial agg per j-group, 4 MB
__device__ float g_Sphi[BB*DD];              // sum_j phi[b,j,d]

// -------- packed fp32x2 helpers (Blackwell PTX-only FFMA2) --------
__device__ __forceinline__ u64 dup2(float x){
    u64 r; asm("mov.b64 %0, {%1, %1};" : "=l"(r) : "f"(x)); return r;
}
__device__ __forceinline__ u64 fma2(u64 a, u64 b, u64 c){
    u64 d; asm("fma.rn.f32x2 %0, %1, %2, %3;" : "=l"(d) : "l"(a), "l"(b), "l"(c)); return d;
}
__device__ __forceinline__ float2 unpk(u64 a){
    float2 r; asm("mov.b64 {%0, %1}, %2;" : "=f"(r.x), "=f"(r.y) : "l"(a)); return r;
}
union F4U { float4 f4; ulonglong2 u2; };

__device__ __forceinline__ float gelu_exact(float x){
    return 0.5f * x * (1.0f + erff(x * 0.7071067811865476f));
}

// ==================== k_prep: A[b,i,f], C[b,i,f] ====================
// grid 256 (b*S rows), 256 threads (f)
__global__ void __launch_bounds__(256) k_prep(const float* __restrict__ q,
                                              const float* __restrict__ gw1,
                                              const float* __restrict__ gb1){
    __shared__ float ph[DD];
    int bi = blockIdx.x;
    int f  = threadIdx.x;
    if (f < DD) ph[f] = q[bi*DD + f];
    __syncthreads();
    float a = 0.f, c = gb1[f];
    #pragma unroll
    for (int d = 0; d < DD; d++){
        float p = ph[d];
        a = fmaf(p, gw1[d*FF + f], a);
        c = fmaf(p, gw1[(DD+d)*FF + f], c);
    }
    g_A[bi*FF + f] = a;
    g_C[bi*FF + f] = c;
}

// ==================== k_sphi: Sphi[b,d] = sum_j phi[b,j,d] ====================
__global__ void k_sphi(const float* __restrict__ q){
    int t = threadIdx.x;            // 128 threads: b = t>>6, d = t&63
    int b = t >> 6, d = t & 63;
    float s = 0.f;
    #pragma unroll 8
    for (int j = 0; j < SS; j++) s += q[(b*SS + j)*DD + d];
    g_Sphi[t] = s;
}

// ==================== k_w: W[b,j,f,e] = sum_d phi[b,j,d]*gw2[f,d*64+e] ====================
// grid 256 (f), 256 threads (t = b*128 + j)
__global__ void __launch_bounds__(256) k_w(const float* __restrict__ q,
                                           const float* __restrict__ gw2){
    __shared__ __align__(16) float g2[DD2];   // gw2 row f: 16 KB
    int f = blockIdx.x;
    int t = threadIdx.x;                      // = b*128 + j
    {
        const float4* src = (const float4*)(gw2 + f*DD2);
        float4* dst = (float4*)g2;
        #pragma unroll
        for (int p = 0; p < 4; p++) dst[p*256 + t] = src[p*256 + t];
    }
    // phi row -> registers (full unroll keeps pr[] in regs)
    float pr[DD];
    const float4* qp = (const float4*)(q + t*DD);
    #pragma unroll
    for (int dd = 0; dd < 16; dd++){
        float4 v = qp[dd];
        pr[dd*4+0]=v.x; pr[dd*4+1]=v.y; pr[dd*4+2]=v.z; pr[dd*4+3]=v.w;
    }
    __syncthreads();
    u64 acc[16][2];
    #pragma unroll
    for (int e4 = 0; e4 < 16; e4++){ acc[e4][0]=0ULL; acc[e4][1]=0ULL; }
    const float4* g24 = (const float4*)g2;
    #pragma unroll
    for (int d = 0; d < DD; d++){
        u64 pd = dup2(pr[d]);
        #pragma unroll
        for (int e4 = 0; e4 < 16; e4++){
            F4U g; g.f4 = g24[d*16 + e4];        // broadcast LDS.128
            acc[e4][0] = fma2(pd, g.u2.x, acc[e4][0]);
            acc[e4][1] = fma2(pd, g.u2.y, acc[e4][1]);
        }
    }
    float4* wout = (float4*)(g_W + ((size_t)t*FF + f)*DD);
    #pragma unroll
    for (int e4 = 0; e4 < 16; e4++){
        F4U o; o.u2.x = acc[e4][0]; o.u2.y = acc[e4][1];
        wout[e4] = o.f4;
    }
}

// ==================== k_main: split-K GEMM with fused gelu ====================
// Pagg[b,jg,i,e] = sum_{j in group} sum_f gelu(A[b,i,f]+C[b,j,f]) * W[b,j,f,e]
// grid (64 jg, 2 b), 256 threads; thread owns 8 i x 4 e.
__global__ void __launch_bounds__(256) k_main(){
    __shared__ __align__(16) float Hs[KC*132];   // H[k][i], padded row 132
    __shared__ __align__(16) float Ws[KC*DD];    // W chunk [k][e]
    int jg = blockIdx.x, b = blockIdx.y;
    int t  = threadIdx.x;
    int e0 = (t & 15) * 4;
    int i0 = (t >> 4) * 8;
    u64 acc[4][4];                                // [e][i-pair]
    #pragma unroll
    for (int x = 0; x < 4; x++)
        #pragma unroll
        for (int y = 0; y < 4; y++) acc[x][y] = 0ULL;

    const float* Arow = g_A + (size_t)b*SS*FF;
    int kk = t & 31;
    int ibase = t >> 5;                           // 0..7

    for (int jj = 0; jj < 2; jj++){
        int j = jg*2 + jj;
        const float* Crow = g_C + ((size_t)b*SS + j)*FF;
        const float* Wrow = g_W + ((size_t)b*SS + j)*FF*DD;
        for (int c = 0; c < FF/KC; c++){
            int f0 = c*KC;
            __syncthreads();                      // previous chunk consumed
            // fill W chunk (contiguous 8 KB)
            {
                const float4* wsrc = (const float4*)(Wrow + f0*DD);
                float4* wdst = (float4*)Ws;
                wdst[t]       = wsrc[t];
                wdst[256 + t] = wsrc[256 + t];
            }
            // fill H chunk: each thread has ONE k, 16 i's
            {
                float cv = Crow[f0 + kk];
                #pragma unroll
                for (int p = 0; p < 16; p++){
                    int i = p*8 + ibase;
                    float a = Arow[i*FF + f0 + kk];
                    Hs[kk*132 + i] = gelu_exact(a + cv);
                }
            }
            __syncthreads();
            // FMA loop
            #pragma unroll 4
            for (int k = 0; k < KC; k++){
                F4U h0, h1;
                h0.f4 = *(const float4*)&Hs[k*132 + i0];
                h1.f4 = *(const float4*)&Hs[k*132 + i0 + 4];
                float4 w = *(const float4*)&Ws[k*DD + e0];
                u64 w0 = dup2(w.x), w1 = dup2(w.y), w2 = dup2(w.z), w3 = dup2(w.w);
                u64 hp0 = h0.u2.x, hp1 = h0.u2.y, hp2 = h1.u2.x, hp3 = h1.u2.y;
                acc[0][0]=fma2(hp0,w0,acc[0][0]); acc[0][1]=fma2(hp1,w0,acc[0][1]);
                acc[0][2]=fma2(hp2,w0,acc[0][2]); acc[0][3]=fma2(hp3,w0,acc[0][3]);
                acc[1][0]=fma2(hp0,w1,acc[1][0]); acc[1][1]=fma2(hp1,w1,acc[1][1]);
                acc[1][2]=fma2(hp2,w1,acc[1][2]); acc[1][3]=fma2(hp3,w1,acc[1][3]);
                acc[2][0]=fma2(hp0,w2,acc[2][0]); acc[2][1]=fma2(hp1,w2,acc[2][1]);
                acc[2][2]=fma2(hp2,w2,acc[2][2]); acc[2][3]=fma2(hp3,w2,acc[2][3]);
                acc[3][0]=fma2(hp0,w3,acc[3][0]); acc[3][1]=fma2(hp1,w3,acc[3][1]);
                acc[3][2]=fma2(hp2,w3,acc[3][2]); acc[3][3]=fma2(hp3,w3,acc[3][3]);
            }
        }
    }
    // write partials (deterministic reduction later)
    float* outp = g_Pagg + ((size_t)(b*NJG + jg)*SS)*DD;
    #pragma unroll
    for (int ip = 0; ip < 4; ip++){
        float2 v0 = unpk(acc[0][ip]), v1 = unpk(acc[1][ip]);
        float2 v2 = unpk(acc[2][ip]), v3 = unpk(acc[3][ip]);
        int ia = i0 + ip*2;
        *(float4*)&outp[(ia  )*DD + e0] = make_float4(v0.x, v1.x, v2.x, v3.x);
        *(float4*)&outp[(ia+1)*DD + e0] = make_float4(v0.y, v1.y, v2.y, v3.y);
    }
}

// ==================== k_epi: reduce partials + LN1 + MLP + LN2 ====================
// grid 256 (b*S rows), 256 threads
__global__ void __launch_bounds__(256) k_epi(const float* __restrict__ q,
                                             const float* __restrict__ gb2,
                                             const float* __restrict__ mw1,
                                             const float* __restrict__ mb1,
                                             const float* __restrict__ mw2,
                                             const float* __restrict__ mb2,
                                             const float* __restrict__ l1g,
                                             const float* __restrict__ l1b,
                                             const float* __restrict__ l2g,
                                             const float* __restrict__ l2b,
                                             float* __restrict__ out){
    __shared__ float ps[4][DD];
    __shared__ float xs[DD];
    __shared__ float ys[DD];
    __shared__ float h2[FF];
    __shared__ float stats[2];
    int bi = blockIdx.x;
    int b = bi >> 7, i = bi & 127;
    int t = threadIdx.x;
    int e = t & 63, p = t >> 6;
    // deterministic reduce over 64 j-groups (4-way thread split, then smem)
    float s = 0.f;
    #pragma unroll
    for (int g = 0; g < 16; g++){
        int jg = p*16 + g;
        s += g_Pagg[((size_t)(b*NJG + jg)*SS + i)*DD + e];
    }
    ps[p][e] = s;
    __syncthreads();
    if (t < DD){
        float agg = ps[0][t] + ps[1][t] + ps[2][t] + ps[3][t];
        float ab = 0.f;                         // gb2 bias term of U
        #pragma unroll
        for (int d = 0; d < DD; d++) ab = fmaf(gb2[d*DD + t], g_Sphi[b*DD + d], ab);
        xs[t] = q[bi*DD + t] + agg + ab;
    }
    __syncthreads();
    // LN1
    if (t < 32){
        float v = xs[t] + xs[t+32];
        #pragma unroll
        for (int o = 16; o > 0; o >>= 1) v += __shfl_xor_sync(0xffffffffu, v, o);
        float mu = v * (1.0f/64.0f);
        float d0 = xs[t]-mu, d1 = xs[t+32]-mu;
        float w = d0*d0 + d1*d1;
        #pragma unroll
        for (int o = 16; o > 0; o >>= 1) w += __shfl_xor_sync(0xffffffffu, w, o);
        if (t == 0){ stats[0] = mu; stats[1] = rsqrtf(w*(1.0f/64.0f) + 1e-5f); }
    }
    __syncthreads();
    if (t < DD) xs[t] = (xs[t]-stats[0])*stats[1]*l1g[t] + l1b[t];
    __syncthreads();
    // MLP fc1 + exact gelu (thread = f)
    {
        float h = mb1[t];
        #pragma unroll
        for (int d = 0; d < DD; d++) h = fmaf(xs[d], mw1[d*FF + t], h);
        h2[t] = gelu_exact(h);
    }
    __syncthreads();
    // fc2 + residual
    if (t < DD){
        float o = mb2[t];
        #pragma unroll 8
        for (int f2 = 0; f2 < FF; f2++) o = fmaf(h2[f2], mw2[f2*DD + t], o);
        ys[t] = xs[t] + o;
    }
    __syncthreads();
    // LN2
    if (t < 32){
        float v = ys[t] + ys[t+32];
        #pragma unroll
        for (int o = 16; o > 0; o >>= 1) v += __shfl_xor_sync(0xffffffffu, v, o);
        float mu = v * (1.0f/64.0f);
        float d0 = ys[t]-mu, d1 = ys[t+32]-mu;
        float w = d0*d0 + d1*d1;
        #pragma unroll
        for (int o = 16; o > 0; o >>= 1) w += __shfl_xor_sync(0xffffffffu, w, o);
        if (t == 0){ stats[0] = mu; stats[1] = rsqrtf(w*(1.0f/64.0f) + 1e-5f); }
    }
    __syncthreads();
    if (t < DD)
        out[bi*DD + t] = (ys[t]-stats[0])*stats[1]*l2g[t] + l2b[t];
}

extern "C" void kernel_launch(void* const* d_in, const int* in_sizes, int n_in,
                              void* d_out, int out_size){
    const float* q   = (const float*)d_in[0];
    const float* gw1 = (const float*)d_in[1];
    const float* gb1 = (const float*)d_in[2];
    const float* gw2 = (const float*)d_in[3];
    const float* gb2 = (const float*)d_in[4];
    const float* mw1 = (const float*)d_in[5];
    const float* mb1 = (const float*)d_in[6];
    const float* mw2 = (const float*)d_in[7];
    const float* mb2 = (const float*)d_in[8];
    const float* l1g = (const float*)d_in[9];
    const float* l1b = (const float*)d_in[10];
    const float* l2g = (const float*)d_in[11];
    const float* l2b = (const float*)d_in[12];
    float* out = (float*)d_out;

    k_prep<<<BB*SS, 256>>>(q, gw1, gb1);
    k_sphi<<<1, 128>>>(q);
    k_w<<<FF, 256>>>(q, gw2);
    k_main<<<dim3(NJG, BB), 256>>>();
    k_epi<<<BB*SS, 256>>>(q, gb2, mw1, mb1, mw2, mb2, l1g, l1b, l2g, l2b, out);
}

// round 2
// speedup vs baseline: 1.3007x; 1.3007x over previous
#include <cuda_runtime.h>
#include <math.h>

// Shapes (fixed by the problem)
#define BB 2
#define SS 128
#define DD 64
#define FF 256
#define DD2 (DD*DD)
#define NJG 128         // j-groups: 1 j per CTA now (was 2) -> grid 256, 2 CTAs/SM
#define KC 32           // f-chunk in main kernel

typedef unsigned long long u64;

// -------- scratch (device globals: sanctioned, no runtime alloc) --------
__device__ float g_A[BB*SS*FF];              // A[b,i,f]
__device__ float g_C[BB*SS*FF];              // C[b,j,f] (includes gb1)
__device__ float g_W[BB*SS*FF*DD];           // W[b,j,f,e]  16 MB
__device__ float g_Pagg[BB*NJG*SS*DD];       // partial agg per j-group, 8 MB
__device__ float g_Sphi[BB*DD];              // sum_j phi[b,j,d]

// -------- packed fp32x2 helpers (Blackwell PTX-only FFMA2) --------
__device__ __forceinline__ u64 dup2(float x){
    u64 r; asm("mov.b64 %0, {%1, %1};" : "=l"(r) : "f"(x)); return r;
}
__device__ __forceinline__ u64 fma2(u64 a, u64 b, u64 c){
    u64 d; asm("fma.rn.f32x2 %0, %1, %2, %3;" : "=l"(d) : "l"(a), "l"(b), "l"(c)); return d;
}
__device__ __forceinline__ float2 unpk(u64 a){
    float2 r; asm("mov.b64 {%0, %1}, %2;" : "=f"(r.x), "=f"(r.y) : "l"(a)); return r;
}
union F4U { float4 f4; ulonglong2 u2; };

__device__ __forceinline__ float gelu_exact(float x){
    return 0.5f * x * (1.0f + erff(x * 0.7071067811865476f));
}

// ==================== k_prep: A[b,i,f], C[b,i,f] ====================
// grid 256 (b*S rows), 256 threads (f)
__global__ void __launch_bounds__(256) k_prep(const float* __restrict__ q,
                                              const float* __restrict__ gw1,
                                              const float* __restrict__ gb1){
    __shared__ float ph[DD];
    int bi = blockIdx.x;
    int f  = threadIdx.x;
    if (f < DD) ph[f] = q[bi*DD + f];
    __syncthreads();
    float a = 0.f, c = gb1[f];
    #pragma unroll
    for (int d = 0; d < DD; d++){
        float p = ph[d];
        a = fmaf(p, gw1[d*FF + f], a);
        c = fmaf(p, gw1[(DD+d)*FF + f], c);
    }
    g_A[bi*FF + f] = a;
    g_C[bi*FF + f] = c;
}

// ==================== k_sphi: Sphi[b,d] = sum_j phi[b,j,d] ====================
__global__ void k_sphi(const float* __restrict__ q){
    int t = threadIdx.x;            // 128 threads: b = t>>6, d = t&63
    int b = t >> 6, d = t & 63;
    float s = 0.f;
    #pragma unroll 8
    for (int j = 0; j < SS; j++) s += q[(b*SS + j)*DD + d];
    g_Sphi[t] = s;
}

// ==================== k_w: W[b,j,f,e] = sum_d phi[b,j,d]*gw2[f,d*64+e] ====================
// grid 256 (f), 256 threads (t = b*128 + j)
__global__ void __launch_bounds__(256) k_w(const float* __restrict__ q,
                                           const float* __restrict__ gw2){
    __shared__ __align__(16) float g2[DD2];   // gw2 row f: 16 KB
    int f = blockIdx.x;
    int t = threadIdx.x;                      // = b*128 + j
    {
        const float4* src = (const float4*)(gw2 + f*DD2);
        float4* dst = (float4*)g2;
        #pragma unroll
        for (int p = 0; p < 4; p++) dst[p*256 + t] = src[p*256 + t];
    }
    // phi row -> registers (full unroll keeps pr[] in regs)
    float pr[DD];
    const float4* qp = (const float4*)(q + t*DD);
    #pragma unroll
    for (int dd = 0; dd < 16; dd++){
        float4 v = qp[dd];
        pr[dd*4+0]=v.x; pr[dd*4+1]=v.y; pr[dd*4+2]=v.z; pr[dd*4+3]=v.w;
    }
    __syncthreads();
    u64 acc[16][2];
    #pragma unroll
    for (int e4 = 0; e4 < 16; e4++){ acc[e4][0]=0ULL; acc[e4][1]=0ULL; }
    const float4* g24 = (const float4*)g2;
    #pragma unroll
    for (int d = 0; d < DD; d++){
        u64 pd = dup2(pr[d]);
        #pragma unroll
        for (int e4 = 0; e4 < 16; e4++){
            F4U g; g.f4 = g24[d*16 + e4];        // broadcast LDS.128
            acc[e4][0] = fma2(pd, g.u2.x, acc[e4][0]);
            acc[e4][1] = fma2(pd, g.u2.y, acc[e4][1]);
        }
    }
    float4* wout = (float4*)(g_W + ((size_t)t*FF + f)*DD);
    #pragma unroll
    for (int e4 = 0; e4 < 16; e4++){
        F4U o; o.u2.x = acc[e4][0]; o.u2.y = acc[e4][1];
        wout[e4] = o.f4;
    }
}

// ==================== k_main: split-K GEMM with fused gelu ====================
// Pagg[b,j,i,e] = sum_f gelu(A[b,i,f]+C[b,j,f]) * W[b,j,f,e]
// grid (128 j, 2 b), 256 threads; thread owns 8 i x 4 e. 1 j per CTA.
__global__ void __launch_bounds__(256) k_main(){
    __shared__ __align__(16) float Hs[KC*132];   // H[k][i], padded row 132
    __shared__ __align__(16) float Ws[KC*DD];    // W chunk [k][e]
    int j = blockIdx.x, b = blockIdx.y;
    int t  = threadIdx.x;
    int e0 = (t & 15) * 4;
    int i0 = (t >> 4) * 8;
    u64 acc[4][4];                                // [e][i-pair]
    #pragma unroll
    for (int x = 0; x < 4; x++)
        #pragma unroll
        for (int y = 0; y < 4; y++) acc[x][y] = 0ULL;

    const float* Arow = g_A + (size_t)b*SS*FF;
    int kk = t & 31;
    int ibase = t >> 5;                           // 0..7

    const float* Crow = g_C + ((size_t)b*SS + j)*FF;
    const float* Wrow = g_W + ((size_t)b*SS + j)*FF*DD;
    for (int c = 0; c < FF/KC; c++){
        int f0 = c*KC;
        __syncthreads();                      // previous chunk consumed
        // fill W chunk (contiguous 8 KB)
        {
            const float4* wsrc = (const float4*)(Wrow + f0*DD);
            float4* wdst = (float4*)Ws;
            wdst[t]       = wsrc[t];
            wdst[256 + t] = wsrc[256 + t];
        }
        // fill H chunk: each thread has ONE k, 16 i's
        {
            float cv = Crow[f0 + kk];
            #pragma unroll
            for (int p = 0; p < 16; p++){
                int i = p*8 + ibase;
                float a = Arow[i*FF + f0 + kk];
                Hs[kk*132 + i] = gelu_exact(a + cv);
            }
        }
        __syncthreads();
        // FMA loop
        #pragma unroll 4
        for (int k = 0; k < KC; k++){
            F4U h0, h1;
            h0.f4 = *(const float4*)&Hs[k*132 + i0];
            h1.f4 = *(const float4*)&Hs[k*132 + i0 + 4];
            float4 w = *(const float4*)&Ws[k*DD + e0];
            u64 w0 = dup2(w.x), w1 = dup2(w.y), w2 = dup2(w.z), w3 = dup2(w.w);
            u64 hp0 = h0.u2.x, hp1 = h0.u2.y, hp2 = h1.u2.x, hp3 = h1.u2.y;
            acc[0][0]=fma2(hp0,w0,acc[0][0]); acc[0][1]=fma2(hp1,w0,acc[0][1]);
            acc[0][2]=fma2(hp2,w0,acc[0][2]); acc[0][3]=fma2(hp3,w0,acc[0][3]);
            acc[1][0]=fma2(hp0,w1,acc[1][0]); acc[1][1]=fma2(hp1,w1,acc[1][1]);
            acc[1][2]=fma2(hp2,w1,acc[1][2]); acc[1][3]=fma2(hp3,w1,acc[1][3]);
            acc[2][0]=fma2(hp0,w2,acc[2][0]); acc[2][1]=fma2(hp1,w2,acc[2][1]);
            acc[2][2]=fma2(hp2,w2,acc[2][2]); acc[2][3]=fma2(hp3,w2,acc[2][3]);
            acc[3][0]=fma2(hp0,w3,acc[3][0]); acc[3][1]=fma2(hp1,w3,acc[3][1]);
            acc[3][2]=fma2(hp2,w3,acc[3][2]); acc[3][3]=fma2(hp3,w3,acc[3][3]);
        }
    }
    // write partials (deterministic reduction later)
    float* outp = g_Pagg + ((size_t)(b*NJG + j)*SS)*DD;
    #pragma unroll
    for (int ip = 0; ip < 4; ip++){
        float2 v0 = unpk(acc[0][ip]), v1 = unpk(acc[1][ip]);
        float2 v2 = unpk(acc[2][ip]), v3 = unpk(acc[3][ip]);
        int ia = i0 + ip*2;
        *(float4*)&outp[(ia  )*DD + e0] = make_float4(v0.x, v1.x, v2.x, v3.x);
        *(float4*)&outp[(ia+1)*DD + e0] = make_float4(v0.y, v1.y, v2.y, v3.y);
    }
}

// ==================== k_epi: reduce partials + LN1 + MLP + LN2 ====================
// grid 256 (b*S rows), 256 threads
__global__ void __launch_bounds__(256) k_epi(const float* __restrict__ q,
                                             const float* __restrict__ gb2,
                                             const float* __restrict__ mw1,
                                             const float* __restrict__ mb1,
                                             const float* __restrict__ mw2,
                                             const float* __restrict__ mb2,
                                             const float* __restrict__ l1g,
                                             const float* __restrict__ l1b,
                                             const float* __restrict__ l2g,
                                             const float* __restrict__ l2b,
                                             float* __restrict__ out){
    __shared__ float ps[4][DD];
    __shared__ float xs[DD];
    __shared__ float ys[DD];
    __shared__ float h2[FF];
    __shared__ float stats[2];
    int bi = blockIdx.x;
    int b = bi >> 7, i = bi & 127;
    int t = threadIdx.x;
    int e = t & 63, p = t >> 6;
    // deterministic reduce over 128 j-groups (4-way thread split, then smem)
    float s = 0.f;
    #pragma unroll
    for (int g = 0; g < 32; g++){
        int jg = p*32 + g;
        s += g_Pagg[((size_t)(b*NJG + jg)*SS + i)*DD + e];
    }
    ps[p][e] = s;
    __syncthreads();
    if (t < DD){
        float agg = ps[0][t] + ps[1][t] + ps[2][t] + ps[3][t];
        float ab = 0.f;                         // gb2 bias term of U
        #pragma unroll
        for (int d = 0; d < DD; d++) ab = fmaf(gb2[d*DD + t], g_Sphi[b*DD + d], ab);
        xs[t] = q[bi*DD + t] + agg + ab;
    }
    __syncthreads();
    // LN1
    if (t < 32){
        float v = xs[t] + xs[t+32];
        #pragma unroll
        for (int o = 16; o > 0; o >>= 1) v += __shfl_xor_sync(0xffffffffu, v, o);
        float mu = v * (1.0f/64.0f);
        float d0 = xs[t]-mu, d1 = xs[t+32]-mu;
        float w = d0*d0 + d1*d1;
        #pragma unroll
        for (int o = 16; o > 0; o >>= 1) w += __shfl_xor_sync(0xffffffffu, w, o);
        if (t == 0){ stats[0] = mu; stats[1] = rsqrtf(w*(1.0f/64.0f) + 1e-5f); }
    }
    __syncthreads();
    if (t < DD) xs[t] = (xs[t]-stats[0])*stats[1]*l1g[t] + l1b[t];
    __syncthreads();
    // MLP fc1 + exact gelu (thread = f)
    {
        float h = mb1[t];
        #pragma unroll
        for (int d = 0; d < DD; d++) h = fmaf(xs[d], mw1[d*FF + t], h);
        h2[t] = gelu_exact(h);
    }
    __syncthreads();
    // fc2 + residual
    if (t < DD){
        float o = mb2[t];
        #pragma unroll 8
        for (int f2 = 0; f2 < FF; f2++) o = fmaf(h2[f2], mw2[f2*DD + t], o);
        ys[t] = xs[t] + o;
    }
    __syncthreads();
    // LN2
    if (t < 32){
        float v = ys[t] + ys[t+32];
        #pragma unroll
        for (int o = 16; o > 0; o >>= 1) v += __shfl_xor_sync(0xffffffffu, v, o);
        float mu = v * (1.0f/64.0f);
        float d0 = ys[t]-mu, d1 = ys[t+32]-mu;
        float w = d0*d0 + d1*d1;
        #pragma unroll
        for (int o = 16; o > 0; o >>= 1) w += __shfl_xor_sync(0xffffffffu, w, o);
        if (t == 0){ stats[0] = mu; stats[1] = rsqrtf(w*(1.0f/64.0f) + 1e-5f); }
    }
    __syncthreads();
    if (t < DD)
        out[bi*DD + t] = (ys[t]-stats[0])*stats[1]*l2g[t] + l2b[t];
}

extern "C" void kernel_launch(void* const* d_in, const int* in_sizes, int n_in,
                              void* d_out, int out_size){
    const float* q   = (const float*)d_in[0];
    const float* gw1 = (const float*)d_in[1];
    const float* gb1 = (const float*)d_in[2];
    const float* gw2 = (const float*)d_in[3];
    const float* gb2 = (const float*)d_in[4];
    const float* mw1 = (const float*)d_in[5];
    const float* mb1 = (const float*)d_in[6];
    const float* mw2 = (const float*)d_in[7];
    const float* mb2 = (const float*)d_in[8];
    const float* l1g = (const float*)d_in[9];
    const float* l1b = (const float*)d_in[10];
    const float* l2g = (const float*)d_in[11];
    const float* l2b = (const float*)d_in[12];
    float* out = (float*)d_out;

    k_prep<<<BB*SS, 256>>>(q, gw1, gb1);
    k_sphi<<<1, 128>>>(q);
    k_w<<<FF, 256>>>(q, gw2);
    k_main<<<dim3(NJG, BB), 256>>>();
    k_epi<<<BB*SS, 256>>>(q, gb2, mw1, mb1, mw2, mb2, l1g, l1b, l2g, l2b, out);
}